// round 13
// baseline (speedup 1.0000x reference)
#include <cuda_runtime.h>
#include <cstdint>
#include <cstddef>

#define SEQ   2048
#define BATCH 64
#define DIN   512
#define HID   512
#define NBLK  128
#define NTHR  512
#define UNITS 4

#define WST   1032   // W row stride floats (258 atoms ≡ 2 mod 8 -> conflict-free)
#define XST   132    // x chunk row stride (2-way conflict ok: slack path)
#define HST   136    // h chunk row stride (34 atoms ≡ 2 mod 8 -> conflict-free)
#define PST   17     // psm row stride

// shared layout (float offsets)
#define SM_W   0
#define SM_X0  16512                    // [64][XST]
#define SM_X1  (SM_X0 + 64*XST)
#define SM_H0  (SM_X1 + 64*XST)        // [64][HST]
#define SM_H1  (SM_H0 + 64*HST)
#define SM_PX  (SM_H1 + 64*HST)        // [2 slot][2 g][64][PST]
#define SM_PH  (SM_PX + 2*2*64*PST)    // [2 g][64][PST]
#define SM_B   (SM_PH + 2*64*PST)      // bias [16]
#define SM_C   (SM_B + 16)             // cell [256]
#define SM_MB  (SM_C + 256)            // 4 mbarriers
#define SM_TOT (SM_MB + 8)
#define SMEM_BYTES (SM_TOT*4)          // 230,496 B

__device__ float    g_h[2][BATCH * HID];
__device__ unsigned g_ctr;
__device__ unsigned g_done;

__device__ __forceinline__ void fma2(unsigned long long& acc,
                                     unsigned long long a, unsigned long long b) {
    asm volatile("fma.rn.f32x2 %0, %1, %2, %0;" : "+l"(acc) : "l"(a), "l"(b));
}
__device__ __forceinline__ float2 unpk(unsigned long long v) {
    float2 f; asm("mov.b64 {%0, %1}, %2;" : "=f"(f.x), "=f"(f.y) : "l"(v)); return f;
}
__device__ __forceinline__ float fsig(float x)  { return 1.0f / (1.0f + __expf(-x)); }
__device__ __forceinline__ float ftanh(float x) { float e = __expf(2.0f*x); return 1.0f - 2.0f/(e+1.0f); }

__device__ __forceinline__ void mbar_init(uint32_t m, unsigned c) {
    asm volatile("mbarrier.init.shared.b64 [%0], %1;" :: "r"(m), "r"(c) : "memory");
}
__device__ __forceinline__ void stage_row(uint32_t dst, const float* src, uint32_t m) {
    asm volatile("mbarrier.arrive.expect_tx.shared::cta.b64 _, [%0], %1;"
                 :: "r"(m), "r"(512u) : "memory");
    asm volatile("cp.async.bulk.shared::cluster.global.mbarrier::complete_tx::bytes "
                 "[%0], [%1], %2, [%3];" :: "r"(dst), "l"(src), "r"(512u), "r"(m) : "memory");
}
__device__ __forceinline__ void mbar_wait(uint32_t m, unsigned par) {
    unsigned done;
    do {
        asm volatile("{\n\t.reg .pred p;\n\t"
                     "mbarrier.try_wait.parity.acquire.cta.shared::cta.b64 p, [%1], %2;\n\t"
                     "selp.b32 %0, 1, 0, p;\n\t}" : "=r"(done) : "r"(m), "r"(par) : "memory");
    } while (!done);
}
__device__ __forceinline__ unsigned ld_acq_gpu(const unsigned* p) {
    unsigned v; asm volatile("ld.acquire.gpu.global.u32 %0, [%1];" : "=r"(v) : "l"(p) : "memory");
    return v;
}
__device__ __forceinline__ void red_release_add(unsigned* p, unsigned v) {
    asm volatile("red.release.gpu.global.add.u32 [%0], %1;" :: "l"(p), "r"(v) : "memory");
}
__device__ __forceinline__ void stcs_f32(float* p, float v) {
    asm volatile("st.global.cs.f32 [%0], %1;" :: "l"(p), "f"(v));
}
__device__ __forceinline__ void barx(int id, int cnt) {
    asm volatile("bar.sync %0, %1;" :: "r"(id), "r"(cnt) : "memory");
}

// one 128-wide chunk, per-thread 32-float K-slice (g-half x khalf interleave)
#define CHUNK_FMA(WB, AB, ASTR)                                                \
    _Pragma("unroll")                                                          \
    for (int kq = 0; kq < 8; ++kq) {                                           \
        ulonglong2 w0 = *(const ulonglong2*)((WB) + 0*4*WST    + kq*8);        \
        ulonglong2 w1 = *(const ulonglong2*)((WB) + 1*4*WST    + kq*8);        \
        ulonglong2 w2 = *(const ulonglong2*)((WB) + 2*4*WST    + kq*8);        \
        ulonglong2 w3 = *(const ulonglong2*)((WB) + 3*4*WST    + kq*8);        \
        ulonglong2 b0 = *(const ulonglong2*)((AB) + 0*4*(ASTR) + kq*8);        \
        ulonglong2 b1 = *(const ulonglong2*)((AB) + 1*4*(ASTR) + kq*8);        \
        ulonglong2 b2 = *(const ulonglong2*)((AB) + 2*4*(ASTR) + kq*8);        \
        ulonglong2 b3 = *(const ulonglong2*)((AB) + 3*4*(ASTR) + kq*8);        \
        fma2(ac[0][0], b0.x, w0.x); fma2(ac[0][0], b0.y, w0.y);                \
        fma2(ac[0][1], b1.x, w0.x); fma2(ac[0][1], b1.y, w0.y);                \
        fma2(ac[0][2], b2.x, w0.x); fma2(ac[0][2], b2.y, w0.y);                \
        fma2(ac[0][3], b3.x, w0.x); fma2(ac[0][3], b3.y, w0.y);                \
        fma2(ac[1][0], b0.x, w1.x); fma2(ac[1][0], b0.y, w1.y);                \
        fma2(ac[1][1], b1.x, w1.x); fma2(ac[1][1], b1.y, w1.y);                \
        fma2(ac[1][2], b2.x, w1.x); fma2(ac[1][2], b2.y, w1.y);                \
        fma2(ac[1][3], b3.x, w1.x); fma2(ac[1][3], b3.y, w1.y);                \
        fma2(ac[2][0], b0.x, w2.x); fma2(ac[2][0], b0.y, w2.y);                \
        fma2(ac[2][1], b1.x, w2.x); fma2(ac[2][1], b1.y, w2.y);                \
        fma2(ac[2][2], b2.x, w2.x); fma2(ac[2][2], b2.y, w2.y);                \
        fma2(ac[2][3], b3.x, w2.x); fma2(ac[2][3], b3.y, w2.y);                \
        fma2(ac[3][0], b0.x, w3.x); fma2(ac[3][0], b0.y, w3.y);                \
        fma2(ac[3][1], b1.x, w3.x); fma2(ac[3][1], b1.y, w3.y);                \
        fma2(ac[3][2], b2.x, w3.x); fma2(ac[3][2], b2.y, w3.y);                \
        fma2(ac[3][3], b3.x, w3.x); fma2(ac[3][3], b3.y, w3.y);                \
    }

#define ACC_CLEAR()                                                            \
    _Pragma("unroll") for (int i = 0; i < 4; ++i)                              \
    _Pragma("unroll") for (int j = 0; j < 4; ++j) ac[i][j] = 0ull;

#define FOLD_PSM(P)                                                            \
    _Pragma("unroll") for (int i = 0; i < 4; ++i)                              \
    _Pragma("unroll") for (int j = 0; j < 4; ++j) {                            \
        float2 v = unpk(ac[i][j]); float s = v.x + v.y;                        \
        s += __shfl_xor_sync(0xffffffffu, s, 16);                              \
        if (khalf == 0)                                                        \
            (P)[(size_t)(g*64 + arow + 4*j)*PST + rgroup + 4*i] = s;           \
    }

__global__ void __launch_bounds__(NTHR, 1)
lstm_kernel(const float* __restrict__ x,
            const float* __restrict__ Wf_, const float* __restrict__ bf_,
            const float* __restrict__ Wi_, const float* __restrict__ bi_,
            const float* __restrict__ Wg_, const float* __restrict__ bg_,
            const float* __restrict__ Wo_, const float* __restrict__ bo_,
            float* __restrict__ out)
{
    extern __shared__ float smem[];
    float* Wsm = smem + SM_W;
    float* X0  = smem + SM_X0;
    float* X1  = smem + SM_X1;
    float* H0  = smem + SM_H0;
    float* H1  = smem + SM_H1;
    float* pxm = smem + SM_PX;
    float* phm = smem + SM_PH;
    float* bsm = smem + SM_B;
    float* csm = smem + SM_C;

    const int tid = threadIdx.x;
    const int bid = blockIdx.x;
    const int j0  = bid * UNITS;

    const uint32_t x0u = (uint32_t)__cvta_generic_to_shared(X0);
    const uint32_t x1u = (uint32_t)__cvta_generic_to_shared(X1);
    const uint32_t h0u = (uint32_t)__cvta_generic_to_shared(H0);
    const uint32_t h1u = (uint32_t)__cvta_generic_to_shared(H1);
    const uint32_t mbx0 = (uint32_t)__cvta_generic_to_shared(smem + SM_MB);
    const uint32_t mbx1 = mbx0 + 8, mbh0 = mbx0 + 16, mbh1 = mbx0 + 24;

    // ---- init ----
    {
        const float* Wptr[4] = { Wf_, Wi_, Wg_, Wo_ };
        for (int idx = tid; idx < 16 * 256; idx += NTHR) {
            int rr = idx >> 8, c4 = idx & 255;
            int u = rr >> 2, gg = rr & 3;
            const float4* src = (const float4*)(Wptr[gg] + (size_t)(j0 + u) * 1024);
            *(float4*)(Wsm + rr * WST + c4 * 4) = src[c4];
        }
        if (tid < 16) {
            int u = tid >> 2, gg = tid & 3;
            const float* bp = (gg==0)?bf_:(gg==1)?bi_:(gg==2)?bg_:bo_;
            bsm[tid] = bp[j0 + u];
        }
        if (tid >= 256) csm[tid - 256] = 0.0f;
        if (tid < 256) {
            int b = tid & 63, u = tid >> 6;
            g_h[0][b * HID + j0 + u] = 0.0f;
            __threadfence();
        }
        if (tid == 0) {
            mbar_init(mbx0, 64); mbar_init(mbx1, 64);
            mbar_init(mbh0, 64); mbar_init(mbh1, 64);
        }
    }
    __syncthreads();
    if (tid == 0) red_release_add(&g_ctr, 1u);   // h0 visible

    // ---- group decomposition (per 256-thread group) ----
    const int gtid   = tid & 255;
    const int g      = gtid >> 7;
    const int wb     = (gtid >> 5) & 3;
    const int lane   = gtid & 31;
    const int khalf  = lane >> 4;
    const int rgroup = (lane >> 2) & 3;
    const int bsub   = lane & 3;
    const int arow   = wb * 16 + bsub;
    const bool stgr  = ((gtid & 3) == 0);
    const int  srow  = gtid >> 2;

    const float* wthr = Wsm + rgroup * WST + g * 64 + khalf * 4;   // + col base per chunk

    if (tid < 256) {
        // ================= X producer group (warps 0-7) =================
        const float* ax[2] = { X0 + (size_t)arow * XST + g * 64 + khalf * 4,
                               X1 + (size_t)arow * XST + g * 64 + khalf * 4 };
        const uint32_t xdst[2] = { x0u + (uint32_t)srow * (XST*4),
                                   x1u + (uint32_t)srow * (XST*4) };
        const uint32_t xmb[2]  = { mbx0, mbx1 };
        unsigned xpar[2] = { 0u, 0u };

        // stage k=0,1
        if (stgr) {
            stage_row(xdst[0], x + (size_t)srow * 512 + 0,   xmb[0]);
            stage_row(xdst[1], x + (size_t)srow * 512 + 128, xmb[1]);
        }

        for (int it = 0; it <= SEQ - 1 + 1; ++it) {   // it = iter index; it==SEQ skipped below
            if (it < SEQ) {
                unsigned long long ac[4][4];
                ACC_CLEAR()
                #pragma unroll
                for (int c = 0; c < 4; ++c) {
                    const int k = it * 4 + c, buf = k & 1;
                    mbar_wait(xmb[buf], xpar[buf]); xpar[buf] ^= 1u;
                    CHUNK_FMA(wthr + c * 128, ax[buf], XST)
                    barx(1, 256);                       // buffer consumed
                    const int kn = k + 2;
                    if (stgr && kn < 4 * SEQ)
                        stage_row(xdst[kn & 1],
                                  x + (size_t)(kn >> 2) * (BATCH*DIN)
                                    + (size_t)srow * 512 + (kn & 3) * 128,
                                  xmb[kn & 1]);
                }
                float* px = pxm + (size_t)(it & 1) * (2*64*PST);
                FOLD_PSM(px)
            }
            barx(3, NTHR);                              // rendezvous R_{it-1}
        }
    } else {
        // ================= H consumer group (warps 8-15) =================
        const float* ah[2] = { H0 + (size_t)arow * HST + g * 64 + khalf * 4,
                               H1 + (size_t)arow * HST + g * 64 + khalf * 4 };
        const uint32_t hdst[2] = { h0u + (uint32_t)srow * (HST*4),
                                   h1u + (uint32_t)srow * (HST*4) };
        const uint32_t hmb[2]  = { mbh0, mbh1 };
        unsigned hpar[2] = { 0u, 0u };
        const int b = gtid & 63, u = gtid >> 6;

        barx(3, NTHR);                                  // pairs X's post-iter0 rendezvous

        for (int t = 0; t < SEQ; ++t) {
            const int p = t & 1;
            const float* __restrict__ hprev = g_h[p];

            if (gtid < 32) {                            // warp 8 polls one line
                const unsigned target = (unsigned)(t + 1) * NBLK;
                while (ld_acq_gpu(&g_ctr) < target) { }
            }
            barx(2, 256);                               // observe propagated to group
            if (stgr) {
                stage_row(hdst[0], hprev + (size_t)srow * 512 + 0,   hmb[0]);
                stage_row(hdst[1], hprev + (size_t)srow * 512 + 128, hmb[1]);
            }

            unsigned long long ac[4][4];
            ACC_CLEAR()

            mbar_wait(hmb[0], hpar[0]); hpar[0] ^= 1u;      // h[0,128)
            CHUNK_FMA(wthr + 512 + 0 * 128, ah[0], HST)
            barx(2, 256);
            if (stgr) stage_row(hdst[0], hprev + (size_t)srow * 512 + 256, hmb[0]);

            mbar_wait(hmb[1], hpar[1]); hpar[1] ^= 1u;      // h[128,256)
            CHUNK_FMA(wthr + 512 + 1 * 128, ah[1], HST)
            barx(2, 256);
            if (stgr) stage_row(hdst[1], hprev + (size_t)srow * 512 + 384, hmb[1]);

            mbar_wait(hmb[0], hpar[0]); hpar[0] ^= 1u;      // h[256,384)
            CHUNK_FMA(wthr + 512 + 2 * 128, ah[0], HST)

            mbar_wait(hmb[1], hpar[1]); hpar[1] ^= 1u;      // h[384,512)
            CHUNK_FMA(wthr + 512 + 3 * 128, ah[1], HST)

            FOLD_PSM(phm)
            barx(2, 256);                               // psm_h visible; bufs consumed

            // epilogue
            {
                const float* px = pxm + (size_t)(t & 1) * (2*64*PST);
                float pre[4];
                #pragma unroll
                for (int gg = 0; gg < 4; ++gg) {
                    int r = u * 4 + gg;
                    pre[gg] = bsm[r]
                            + px[(size_t)(0*64 + b) * PST + r]
                            + px[(size_t)(1*64 + b) * PST + r]
                            + phm[(size_t)(0*64 + b) * PST + r]
                            + phm[(size_t)(1*64 + b) * PST + r];
                }
                float fg  = fsig(pre[0]);
                float ig  = fsig(pre[1]);
                float gg2 = ftanh(pre[2]);
                float og  = fsig(pre[3]);
                float cv  = fg * csm[gtid] + ig * gg2;
                csm[gtid] = cv;
                float hv  = og * ftanh(cv);
                g_h[p ^ 1][b * HID + j0 + u] = hv;
                __threadfence();
                barx(2, 256);                           // all h stores drained
                if (gtid == 0) red_release_add(&g_ctr, 1u);

                stcs_f32(&out[((size_t)t * BATCH + b) * HID + j0 + u], hv);
                if (t == SEQ - 1) {
                    size_t base = (size_t)SEQ * BATCH * HID;
                    stcs_f32(&out[base + (size_t)b * HID + j0 + u], hv);
                    stcs_f32(&out[base + (size_t)BATCH * HID + (size_t)b * HID + j0 + u], cv);
                }
            }
            barx(3, NTHR);                              // rendezvous R_t
        }
    }

    // ---- reset persistent state for the next graph replay ----
    __syncthreads();
    if (tid == 0) {
        __threadfence();
        if (atomicAdd(&g_done, 1u) == NBLK - 1) {
            g_done = 0u;
            atomicExch(&g_ctr, 0u);
            __threadfence();
        }
    }
}

extern "C" void kernel_launch(void* const* d_in, const int* in_sizes, int n_in,
                              void* d_out, int out_size)
{
    const float* x  = (const float*)d_in[0];
    const float* Wf = (const float*)d_in[1];
    const float* bf = (const float*)d_in[2];
    const float* Wi = (const float*)d_in[3];
    const float* bi = (const float*)d_in[4];
    const float* Wg = (const float*)d_in[5];
    const float* bg = (const float*)d_in[6];
    const float* Wo = (const float*)d_in[7];
    const float* bo = (const float*)d_in[8];
    float* out = (float*)d_out;

    cudaFuncSetAttribute(lstm_kernel,
                         cudaFuncAttributeMaxDynamicSharedMemorySize, SMEM_BYTES);
    lstm_kernel<<<NBLK, NTHR, SMEM_BYTES>>>(x, Wf, bf, Wi, bi, Wg, bg, Wo, bo, out);
}

// round 14
// speedup vs baseline: 1.0067x; 1.0067x over previous
#include <cuda_runtime.h>
#include <cstdint>
#include <cstddef>

#define SEQ   2048
#define BATCH 64
#define DIN   512
#define HID   512
#define NBLK  128
#define NTHR  512
#define UNITS 4

#define WST   1032   // W row stride floats (258 atoms ≡ 2 mod 8 -> conflict-free)
#define XST   132    // x chunk row stride (2-way conflict ok: slack path)
#define HST   136    // h chunk row stride (34 atoms ≡ 2 mod 8 -> conflict-free)
#define PST   17     // psm row stride

// shared layout (float offsets)
#define SM_W   0
#define SM_X0  16512                    // [64][XST]
#define SM_X1  (SM_X0 + 64*XST)
#define SM_H0  (SM_X1 + 64*XST)        // [64][HST]
#define SM_H1  (SM_H0 + 64*HST)
#define SM_PX  (SM_H1 + 64*HST)        // [2 slot][2 g][64][PST]
#define SM_PH  (SM_PX + 2*2*64*PST)    // [2 g][64][PST]
#define SM_B   (SM_PH + 2*64*PST)      // bias [16]
#define SM_C   (SM_B + 16)             // cell [256]
#define SM_MB  (SM_C + 256)            // 4 mbarriers
#define SM_TOT (SM_MB + 8)
#define SMEM_BYTES (SM_TOT*4)          // 230,496 B

__device__ float    g_h[2][BATCH * HID];
__device__ unsigned g_ctr;
__device__ unsigned g_done;

__device__ __forceinline__ void fma2(unsigned long long& acc,
                                     unsigned long long a, unsigned long long b) {
    asm volatile("fma.rn.f32x2 %0, %1, %2, %0;" : "+l"(acc) : "l"(a), "l"(b));
}
__device__ __forceinline__ float2 unpk(unsigned long long v) {
    float2 f; asm("mov.b64 {%0, %1}, %2;" : "=f"(f.x), "=f"(f.y) : "l"(v)); return f;
}
__device__ __forceinline__ float fsig(float x)  { return 1.0f / (1.0f + __expf(-x)); }
__device__ __forceinline__ float ftanh(float x) { float e = __expf(2.0f*x); return 1.0f - 2.0f/(e+1.0f); }

__device__ __forceinline__ void mbar_init(uint32_t m, unsigned c) {
    asm volatile("mbarrier.init.shared.b64 [%0], %1;" :: "r"(m), "r"(c) : "memory");
}
__device__ __forceinline__ void stage_row(uint32_t dst, const float* src, uint32_t m) {
    asm volatile("mbarrier.arrive.expect_tx.shared::cta.b64 _, [%0], %1;"
                 :: "r"(m), "r"(512u) : "memory");
    asm volatile("cp.async.bulk.shared::cluster.global.mbarrier::complete_tx::bytes "
                 "[%0], [%1], %2, [%3];" :: "r"(dst), "l"(src), "r"(512u), "r"(m) : "memory");
}
__device__ __forceinline__ void mbar_wait(uint32_t m, unsigned par) {
    unsigned done;
    do {
        asm volatile("{\n\t.reg .pred p;\n\t"
                     "mbarrier.try_wait.parity.acquire.cta.shared::cta.b64 p, [%1], %2;\n\t"
                     "selp.b32 %0, 1, 0, p;\n\t}" : "=r"(done) : "r"(m), "r"(par) : "memory");
    } while (!done);
}
__device__ __forceinline__ unsigned ld_acq_gpu(const unsigned* p) {
    unsigned v; asm volatile("ld.acquire.gpu.global.u32 %0, [%1];" : "=r"(v) : "l"(p) : "memory");
    return v;
}
__device__ __forceinline__ void red_release_add(unsigned* p, unsigned v) {
    asm volatile("red.release.gpu.global.add.u32 [%0], %1;" :: "l"(p), "r"(v) : "memory");
}
__device__ __forceinline__ void stcs_f32(float* p, float v) {
    asm volatile("st.global.cs.f32 [%0], %1;" :: "l"(p), "f"(v));
}
__device__ __forceinline__ void barx(int id, int cnt) {
    asm volatile("bar.sync %0, %1;" :: "r"(id), "r"(cnt) : "memory");
}

// one 128-wide chunk, per-thread 32-float K-slice (g-half x khalf interleave)
#define CHUNK_FMA(WB, AB, ASTR)                                                \
    _Pragma("unroll")                                                          \
    for (int kq = 0; kq < 8; ++kq) {                                           \
        ulonglong2 w0 = *(const ulonglong2*)((WB) + 0*4*WST    + kq*8);        \
        ulonglong2 w1 = *(const ulonglong2*)((WB) + 1*4*WST    + kq*8);        \
        ulonglong2 w2 = *(const ulonglong2*)((WB) + 2*4*WST    + kq*8);        \
        ulonglong2 w3 = *(const ulonglong2*)((WB) + 3*4*WST    + kq*8);        \
        ulonglong2 b0 = *(const ulonglong2*)((AB) + 0*4*(ASTR) + kq*8);        \
        ulonglong2 b1 = *(const ulonglong2*)((AB) + 1*4*(ASTR) + kq*8);        \
        ulonglong2 b2 = *(const ulonglong2*)((AB) + 2*4*(ASTR) + kq*8);        \
        ulonglong2 b3 = *(const ulonglong2*)((AB) + 3*4*(ASTR) + kq*8);        \
        fma2(ac[0][0], b0.x, w0.x); fma2(ac[0][0], b0.y, w0.y);                \
        fma2(ac[0][1], b1.x, w0.x); fma2(ac[0][1], b1.y, w0.y);                \
        fma2(ac[0][2], b2.x, w0.x); fma2(ac[0][2], b2.y, w0.y);                \
        fma2(ac[0][3], b3.x, w0.x); fma2(ac[0][3], b3.y, w0.y);                \
        fma2(ac[1][0], b0.x, w1.x); fma2(ac[1][0], b0.y, w1.y);                \
        fma2(ac[1][1], b1.x, w1.x); fma2(ac[1][1], b1.y, w1.y);                \
        fma2(ac[1][2], b2.x, w1.x); fma2(ac[1][2], b2.y, w1.y);                \
        fma2(ac[1][3], b3.x, w1.x); fma2(ac[1][3], b3.y, w1.y);                \
        fma2(ac[2][0], b0.x, w2.x); fma2(ac[2][0], b0.y, w2.y);                \
        fma2(ac[2][1], b1.x, w2.x); fma2(ac[2][1], b1.y, w2.y);                \
        fma2(ac[2][2], b2.x, w2.x); fma2(ac[2][2], b2.y, w2.y);                \
        fma2(ac[2][3], b3.x, w2.x); fma2(ac[2][3], b3.y, w2.y);                \
        fma2(ac[3][0], b0.x, w3.x); fma2(ac[3][0], b0.y, w3.y);                \
        fma2(ac[3][1], b1.x, w3.x); fma2(ac[3][1], b1.y, w3.y);                \
        fma2(ac[3][2], b2.x, w3.x); fma2(ac[3][2], b2.y, w3.y);                \
        fma2(ac[3][3], b3.x, w3.x); fma2(ac[3][3], b3.y, w3.y);                \
    }

#define ACC_CLEAR()                                                            \
    _Pragma("unroll") for (int i = 0; i < 4; ++i)                              \
    _Pragma("unroll") for (int j = 0; j < 4; ++j) ac[i][j] = 0ull;

#define FOLD_PSM(P)                                                            \
    _Pragma("unroll") for (int i = 0; i < 4; ++i)                              \
    _Pragma("unroll") for (int j = 0; j < 4; ++j) {                            \
        float2 v = unpk(ac[i][j]); float s = v.x + v.y;                        \
        s += __shfl_xor_sync(0xffffffffu, s, 16);                              \
        if (khalf == 0)                                                        \
            (P)[(size_t)(g*64 + arow + 4*j)*PST + rgroup + 4*i] = s;           \
    }

__global__ void __launch_bounds__(NTHR, 1)
lstm_kernel(const float* __restrict__ x,
            const float* __restrict__ Wf_, const float* __restrict__ bf_,
            const float* __restrict__ Wi_, const float* __restrict__ bi_,
            const float* __restrict__ Wg_, const float* __restrict__ bg_,
            const float* __restrict__ Wo_, const float* __restrict__ bo_,
            float* __restrict__ out)
{
    extern __shared__ float smem[];
    float* Wsm = smem + SM_W;
    float* X0  = smem + SM_X0;
    float* X1  = smem + SM_X1;
    float* H0  = smem + SM_H0;
    float* H1  = smem + SM_H1;
    float* pxm = smem + SM_PX;
    float* phm = smem + SM_PH;
    float* bsm = smem + SM_B;
    float* csm = smem + SM_C;

    const int tid = threadIdx.x;
    const int bid = blockIdx.x;
    const int j0  = bid * UNITS;

    const uint32_t x0u = (uint32_t)__cvta_generic_to_shared(X0);
    const uint32_t x1u = (uint32_t)__cvta_generic_to_shared(X1);
    const uint32_t h0u = (uint32_t)__cvta_generic_to_shared(H0);
    const uint32_t h1u = (uint32_t)__cvta_generic_to_shared(H1);
    const uint32_t mbx0 = (uint32_t)__cvta_generic_to_shared(smem + SM_MB);
    const uint32_t mbx1 = mbx0 + 8, mbh0 = mbx0 + 16, mbh1 = mbx0 + 24;

    // ---- init ----
    {
        const float* Wptr[4] = { Wf_, Wi_, Wg_, Wo_ };
        for (int idx = tid; idx < 16 * 256; idx += NTHR) {
            int rr = idx >> 8, c4 = idx & 255;
            int u = rr >> 2, gg = rr & 3;
            const float4* src = (const float4*)(Wptr[gg] + (size_t)(j0 + u) * 1024);
            *(float4*)(Wsm + rr * WST + c4 * 4) = src[c4];
        }
        if (tid < 16) {
            int u = tid >> 2, gg = tid & 3;
            const float* bp = (gg==0)?bf_:(gg==1)?bi_:(gg==2)?bg_:bo_;
            bsm[tid] = bp[j0 + u];
        }
        if (tid >= 256) csm[tid - 256] = 0.0f;
        if (tid < 256) {
            int b = tid & 63, u = tid >> 6;
            g_h[0][b * HID + j0 + u] = 0.0f;
            __threadfence();
        }
        if (tid == 0) {
            mbar_init(mbx0, 64); mbar_init(mbx1, 64);
            mbar_init(mbh0, 64); mbar_init(mbh1, 64);
        }
    }
    __syncthreads();
    if (tid == 0) red_release_add(&g_ctr, 1u);   // h0 visible

    // ---- group decomposition (per 256-thread group) ----
    const int gtid   = tid & 255;
    const int g      = gtid >> 7;
    const int wb     = (gtid >> 5) & 3;
    const int lane   = gtid & 31;
    const int khalf  = lane >> 4;
    const int rgroup = (lane >> 2) & 3;
    const int bsub   = lane & 3;
    const int arow   = wb * 16 + bsub;
    const bool stgr  = ((gtid & 3) == 0);
    const int  srow  = gtid >> 2;

    const float* wthr = Wsm + rgroup * WST + g * 64 + khalf * 4;   // + col base per chunk

    if (tid < 256) {
        // ================= X producer group (warps 0-7) =================
        const float* ax[2] = { X0 + (size_t)arow * XST + g * 64 + khalf * 4,
                               X1 + (size_t)arow * XST + g * 64 + khalf * 4 };
        const uint32_t xdst[2] = { x0u + (uint32_t)srow * (XST*4),
                                   x1u + (uint32_t)srow * (XST*4) };
        const uint32_t xmb[2]  = { mbx0, mbx1 };
        unsigned xpar[2] = { 0u, 0u };

        // stage k=0,1
        if (stgr) {
            stage_row(xdst[0], x + (size_t)srow * 512 + 0,   xmb[0]);
            stage_row(xdst[1], x + (size_t)srow * 512 + 128, xmb[1]);
        }

        for (int it = 0; it <= SEQ - 1 + 1; ++it) {   // it = iter index; it==SEQ skipped below
            if (it < SEQ) {
                unsigned long long ac[4][4];
                ACC_CLEAR()
                #pragma unroll
                for (int c = 0; c < 4; ++c) {
                    const int k = it * 4 + c, buf = k & 1;
                    mbar_wait(xmb[buf], xpar[buf]); xpar[buf] ^= 1u;
                    CHUNK_FMA(wthr + c * 128, ax[buf], XST)
                    barx(1, 256);                       // buffer consumed
                    const int kn = k + 2;
                    if (stgr && kn < 4 * SEQ)
                        stage_row(xdst[kn & 1],
                                  x + (size_t)(kn >> 2) * (BATCH*DIN)
                                    + (size_t)srow * 512 + (kn & 3) * 128,
                                  xmb[kn & 1]);
                }
                float* px = pxm + (size_t)(it & 1) * (2*64*PST);
                FOLD_PSM(px)
            }
            barx(3, NTHR);                              // rendezvous R_{it-1}
        }
    } else {
        // ================= H consumer group (warps 8-15) =================
        const float* ah[2] = { H0 + (size_t)arow * HST + g * 64 + khalf * 4,
                               H1 + (size_t)arow * HST + g * 64 + khalf * 4 };
        const uint32_t hdst[2] = { h0u + (uint32_t)srow * (HST*4),
                                   h1u + (uint32_t)srow * (HST*4) };
        const uint32_t hmb[2]  = { mbh0, mbh1 };
        unsigned hpar[2] = { 0u, 0u };
        const int b = gtid & 63, u = gtid >> 6;

        barx(3, NTHR);                                  // pairs X's post-iter0 rendezvous

        for (int t = 0; t < SEQ; ++t) {
            const int p = t & 1;
            const float* __restrict__ hprev = g_h[p];

            if (gtid < 32) {                            // warp 8 polls one line
                const unsigned target = (unsigned)(t + 1) * NBLK;
                while (ld_acq_gpu(&g_ctr) < target) { }
            }
            barx(2, 256);                               // observe propagated to group
            if (stgr) {
                stage_row(hdst[0], hprev + (size_t)srow * 512 + 0,   hmb[0]);
                stage_row(hdst[1], hprev + (size_t)srow * 512 + 128, hmb[1]);
            }

            unsigned long long ac[4][4];
            ACC_CLEAR()

            mbar_wait(hmb[0], hpar[0]); hpar[0] ^= 1u;      // h[0,128)
            CHUNK_FMA(wthr + 512 + 0 * 128, ah[0], HST)
            barx(2, 256);
            if (stgr) stage_row(hdst[0], hprev + (size_t)srow * 512 + 256, hmb[0]);

            mbar_wait(hmb[1], hpar[1]); hpar[1] ^= 1u;      // h[128,256)
            CHUNK_FMA(wthr + 512 + 1 * 128, ah[1], HST)
            barx(2, 256);
            if (stgr) stage_row(hdst[1], hprev + (size_t)srow * 512 + 384, hmb[1]);

            mbar_wait(hmb[0], hpar[0]); hpar[0] ^= 1u;      // h[256,384)
            CHUNK_FMA(wthr + 512 + 2 * 128, ah[0], HST)

            mbar_wait(hmb[1], hpar[1]); hpar[1] ^= 1u;      // h[384,512)
            CHUNK_FMA(wthr + 512 + 3 * 128, ah[1], HST)

            FOLD_PSM(phm)
            barx(2, 256);                               // psm_h visible; bufs consumed

            // epilogue
            {
                const float* px = pxm + (size_t)(t & 1) * (2*64*PST);
                float pre[4];
                #pragma unroll
                for (int gg = 0; gg < 4; ++gg) {
                    int r = u * 4 + gg;
                    pre[gg] = bsm[r]
                            + px[(size_t)(0*64 + b) * PST + r]
                            + px[(size_t)(1*64 + b) * PST + r]
                            + phm[(size_t)(0*64 + b) * PST + r]
                            + phm[(size_t)(1*64 + b) * PST + r];
                }
                float fg  = fsig(pre[0]);
                float ig  = fsig(pre[1]);
                float gg2 = ftanh(pre[2]);
                float og  = fsig(pre[3]);
                float cv  = fg * csm[gtid] + ig * gg2;
                csm[gtid] = cv;
                float hv  = og * ftanh(cv);
                g_h[p ^ 1][b * HID + j0 + u] = hv;
                __threadfence();
                barx(2, 256);                           // all h stores drained
                if (gtid == 0) red_release_add(&g_ctr, 1u);

                stcs_f32(&out[((size_t)t * BATCH + b) * HID + j0 + u], hv);
                if (t == SEQ - 1) {
                    size_t base = (size_t)SEQ * BATCH * HID;
                    stcs_f32(&out[base + (size_t)b * HID + j0 + u], hv);
                    stcs_f32(&out[base + (size_t)BATCH * HID + (size_t)b * HID + j0 + u], cv);
                }
            }
            barx(3, NTHR);                              // rendezvous R_t
        }
    }

    // ---- reset persistent state for the next graph replay ----
    __syncthreads();
    if (tid == 0) {
        __threadfence();
        if (atomicAdd(&g_done, 1u) == NBLK - 1) {
            g_done = 0u;
            atomicExch(&g_ctr, 0u);
            __threadfence();
        }
    }
}

extern "C" void kernel_launch(void* const* d_in, const int* in_sizes, int n_in,
                              void* d_out, int out_size)
{
    const float* x  = (const float*)d_in[0];
    const float* Wf = (const float*)d_in[1];
    const float* bf = (const float*)d_in[2];
    const float* Wi = (const float*)d_in[3];
    const float* bi = (const float*)d_in[4];
    const float* Wg = (const float*)d_in[5];
    const float* bg = (const float*)d_in[6];
    const float* Wo = (const float*)d_in[7];
    const float* bo = (const float*)d_in[8];
    float* out = (float*)d_out;

    cudaFuncSetAttribute(lstm_kernel,
                         cudaFuncAttributeMaxDynamicSharedMemorySize, SMEM_BYTES);
    lstm_kernel<<<NBLK, NTHR, SMEM_BYTES>>>(x, Wf, bf, Wi, bi, Wg, bg, Wo, bo, out);
}